// round 4
// baseline (speedup 1.0000x reference)
#include <cuda_runtime.h>
#include <cstdint>
#include <math.h>

// ---------------- problem constants ----------------
#define FSR    44100.0
#define NS     131072            // samples per channel
#define NCHAN  32                // 4*8 channels
#define CHUNK  32                // samples per chunk (cascade decomposition)
#define NCH    (NS/CHUNK)        // 4096 chunks per channel
#define NSB    64                // superchunks
#define SBC    (NCH/NSB)         // 64 chunks per superchunk
#define EU     32                // envelope block size
#define ENB    (NS/EU)           // 4096 envelope blocks
#define NLINES 33                // EU+1 slope classes
#define EG     16                // env2 blocks per load group
#define CSH    512.0f            // positivity shift for u32-max trick

// ---------------- device scratch (static, no allocs) ----------------
__device__ float g_bufA[NCHAN * NS];        // 16 MB : x-gained
__device__ float g_bufB[NCHAN * NS];        // 16 MB : y (post-EQ)
__device__ float g_gc  [NCHAN * NS];        // 16 MB : static gain curve
__device__ float g_int [ENB * NLINES * NCHAN]; // 17.3 MB : intercepts [b][line][chan]
__device__ float g_hb  [ENB * NCHAN];       // 0.5 MB : block-boundary h
__device__ float g_slope[NCHAN][NLINES];
__device__ float g_offT [NLINES][NCHAN];    // C*(1-S) per line, transposed
__device__ float g_d12   [NCH * NCHAN * 12];
__device__ float g_start12[NCH * NCHAN * 12];
__device__ float g_T     [NSB * NCHAN * 12];
__device__ float g_sbst  [NSB * NCHAN * 12];
__device__ float g_ML[NCHAN][144];             // M^CHUNK
__device__ float g_MS[NCHAN][144];             // M^(CHUNK*SBC)

struct ChParams {
    float b0[6], b1[6], b2[6], a1[6], a2[6];
    float gain;
    float thr, qr, k2, kk, inv2k;      // compressor static curve
    float aa, ar, ka, kr, sigma, mk;   // envelope
    float cth, sth;                    // pan
};
__device__ ChParams g_par[NCHAN];

__device__ const float PLO[26] = {-24.f,-20.f,20.f,0.1f,-20.f,80.f,0.1f,-20.f,200.f,0.1f,-20.f,500.f,0.1f,
                                  -20.f,1000.f,0.1f,-20.f,4000.f,0.1f,-60.f,1.f,1.f,10.f,0.1f,0.f,0.f};
__device__ const float PHI[26] = {24.f,20.f,2000.f,6.f,20.f,2000.f,6.f,20.f,4000.f,6.f,20.f,8000.f,6.f,
                                  20.f,12000.f,6.f,20.f,18000.f,6.f,0.f,10.f,100.f,1000.f,24.f,12.f,1.f};

// ---------------- coefficient setup (32 threads) ----------------
__device__ inline void store_norm(ChParams& P, int s, double b0d, double b1d, double b2d,
                                  double a0d, double a1d, double a2d) {
    P.b0[s] = (float)(b0d / a0d);
    P.b1[s] = (float)(b1d / a0d);
    P.b2[s] = (float)(b2d / a0d);
    P.a1[s] = (float)(a1d / a0d);
    P.a2[s] = (float)(a2d / a0d);
}

__device__ inline void shelf_coeffs(ChParams& P, int s, double g, double f, double q, double sgn) {
    double A  = pow(10.0, g / 40.0);
    double w0 = 2.0 * M_PI * f / FSR;
    double cw = cos(w0), sw = sin(w0);
    double alpha = sw / (2.0 * q);
    double s2 = 2.0 * sqrt(A) * alpha;
    double b0 = A * (A + 1.0 - sgn * (A - 1.0) * cw + s2);
    double b1 = sgn * 2.0 * A * (A - 1.0 - sgn * (A + 1.0) * cw);
    double b2 = A * (A + 1.0 - sgn * (A - 1.0) * cw - s2);
    double a0 = A + 1.0 + sgn * (A - 1.0) * cw + s2;
    double a1 = -sgn * 2.0 * (A - 1.0 + sgn * (A + 1.0) * cw);
    double a2 = A + 1.0 + sgn * (A - 1.0) * cw - s2;
    store_norm(P, s, b0, b1, b2, a0, a1, a2);
}

__device__ inline void peak_coeffs(ChParams& P, int s, double g, double f, double q) {
    double A  = pow(10.0, g / 40.0);
    double w0 = 2.0 * M_PI * f / FSR;
    double cw = cos(w0), sw = sin(w0);
    double alpha = sw / (2.0 * q);
    store_norm(P, s, 1.0 + alpha * A, -2.0 * cw, 1.0 - alpha * A,
                     1.0 + alpha / A, -2.0 * cw, 1.0 - alpha / A);
}

__global__ void k_coef(const float* __restrict__ mp) {
    int c = threadIdx.x;
    if (c >= NCHAN) return;
    double p[26];
#pragma unroll
    for (int i = 0; i < 26; i++) {
        double lo = PLO[i], hi = PHI[i];
        p[i] = (double)mp[c * 26 + i] * (hi - lo) + lo;
    }
    ChParams P;
    P.gain = (float)pow(10.0, p[0] / 20.0);
    shelf_coeffs(P, 0, p[1],  p[2],  p[3],  +1.0);
    peak_coeffs (P, 1, p[4],  p[5],  p[6]);
    peak_coeffs (P, 2, p[7],  p[8],  p[9]);
    peak_coeffs (P, 3, p[10], p[11], p[12]);
    peak_coeffs (P, 4, p[13], p[14], p[15]);
    shelf_coeffs(P, 5, p[16], p[17], p[18], -1.0);

    P.thr  = (float)p[19];
    P.qr   = (float)(1.0 / p[20] - 1.0);
    P.kk   = (float)p[23];
    P.k2   = (float)(p[23] * 0.5);
    P.inv2k= (float)(1.0 / (2.0 * p[23]));
    float aa = (float)exp(-1.0 / (FSR * p[21] * 0.001));
    float ar = (float)exp(-1.0 / (FSR * p[22] * 0.001));
    float omaa = 1.0f - aa;   // replicate reference fp32 rounding
    float omar = 1.0f - ar;
    float sg = (aa >= ar) ? 1.0f : -1.0f;
    P.aa = aa; P.ar = ar;
    P.sigma = sg; P.ka = sg * omaa; P.kr = sg * omar;
    P.mk = (float)p[24];
    double th = p[25] * (M_PI * 0.5);
    P.cth = (float)cos(th);
    P.sth = (float)sin(th);
    g_par[c] = P;
#pragma unroll
    for (int i = 0; i < NLINES; i++) {
        double s = pow((double)aa, (double)i) * pow((double)ar, (double)(EU - i));
        g_slope[c][i] = (float)s;
        g_offT[i][c]  = (float)((double)CSH * (1.0 - s));
    }
}

// ---------------- build M^CHUNK, M^(CHUNK*SBC) per channel (warp/channel) ----------------
__device__ void warp_matmul(double* dst, const double* src, int l) {
    for (int e = l; e < 144; e += 32) {
        int r = e / 12, c2 = e % 12;
        double acc = 0.0;
#pragma unroll
        for (int k = 0; k < 12; k++) acc += src[r * 12 + k] * src[k * 12 + c2];
        dst[e] = acc;
    }
}

__global__ void k_msetup() {          // <<<4, 256>>>
    __shared__ double SA[8][144], SB[8][144];
    int w = threadIdx.x >> 5, l = threadIdx.x & 31;
    int ch = blockIdx.x * 8 + w;
    double* cur = SA[w];
    double* alt = SB[w];
    const ChParams& P = g_par[ch];
    if (l < 12) {
        double s[12], ns[12];
#pragma unroll
        for (int i = 0; i < 12; i++) s[i] = (i == l) ? 1.0 : 0.0;
        double in = 0.0;
#pragma unroll
        for (int st = 0; st < 6; st++) {
            double y = (double)P.b0[st] * in + s[2 * st];
            ns[2 * st]     = (double)P.b1[st] * in - (double)P.a1[st] * y + s[2 * st + 1];
            ns[2 * st + 1] = (double)P.b2[st] * in - (double)P.a2[st] * y;
            in = y;
        }
#pragma unroll
        for (int i = 0; i < 12; i++) cur[i * 12 + l] = ns[i];
    }
    __syncwarp();
    // squarings: M^(2^q); store at q=5 (M^32) and q=11 (M^2048)
    for (int q = 1; q <= 11; q++) {
        warp_matmul(alt, cur, l);
        __syncwarp();
        double* t = cur; cur = alt; alt = t;
        if (q == 5)
            for (int e = l; e < 144; e += 32) g_ML[ch][e] = (float)cur[e];
    }
    for (int e = l; e < 144; e += 32) g_MS[ch][e] = (float)cur[e];
}

// ---------------- transpose [c][t] -> [t][c] with input gain ----------------
__global__ void k_transpose(const float* __restrict__ tracks) {
    __shared__ float tile[32][33];
    int t0 = blockIdx.x * 32;
    int tx = threadIdx.x, ty = threadIdx.y;   // (32, 8)
#pragma unroll
    for (int i = 0; i < 4; i++) {
        int row = ty + i * 8;
        tile[row][tx] = tracks[(size_t)row * NS + t0 + tx];
    }
    __syncthreads();
#pragma unroll
    for (int i = 0; i < 4; i++) {
        int row = ty + i * 8;
        g_bufA[(size_t)(t0 + row) * NCHAN + tx] = tile[tx][row] * g_par[tx].gain;
    }
}

// ---------------- cascade pass 1: zero-init responses ----------------
__global__ void k_pass1(const float* __restrict__ in) {
    int c = threadIdx.x;
    int k = blockIdx.x * blockDim.y + threadIdx.y;
    const ChParams& P = g_par[c];
    float b0[6], b1[6], b2[6], a1[6], a2[6];
#pragma unroll
    for (int s = 0; s < 6; s++) { b0[s]=P.b0[s]; b1[s]=P.b1[s]; b2[s]=P.b2[s]; a1[s]=P.a1[s]; a2[s]=P.a2[s]; }
    float s1[6] = {0,0,0,0,0,0}, s2[6] = {0,0,0,0,0,0};
    const float* ip = in + (size_t)k * CHUNK * NCHAN + c;
#pragma unroll 8
    for (int t = 0; t < CHUNK; t++) {
        float v = ip[(size_t)t * NCHAN];
#pragma unroll
        for (int s = 0; s < 6; s++) {
            float y = fmaf(b0[s], v, s1[s]);
            s1[s] = fmaf(-a1[s], y, fmaf(b1[s], v, s2[s]));
            s2[s] = fmaf(-a2[s], y, b2[s] * v);
            v = y;
        }
    }
    float* d = g_d12 + ((size_t)k * NCHAN + c) * 12;
#pragma unroll
    for (int s = 0; s < 6; s++) { d[2*s] = s1[s]; d[2*s+1] = s2[s]; }
}

// ---------------- hierarchical 12-state scan ----------------
__global__ void __launch_bounds__(256) k_scanA() {
    int idx = blockIdx.x * blockDim.x + threadIdx.x;   // NSB*NCHAN
    int ch = idx & (NCHAN - 1), sb = idx >> 5;
    float M[144];
#pragma unroll
    for (int e = 0; e < 144; e++) M[e] = g_ML[ch][e];
    float S[12];
#pragma unroll
    for (int i = 0; i < 12; i++) S[i] = 0.f;
    for (int j = 0; j < SBC; j++) {
        const float* d = g_d12 + ((size_t)(sb * SBC + j) * NCHAN + ch) * 12;
        float ns[12];
#pragma unroll
        for (int r = 0; r < 12; r++) {
            float acc = d[r];
#pragma unroll
            for (int k2 = 0; k2 < 12; k2++) acc = fmaf(M[r * 12 + k2], S[k2], acc);
            ns[r] = acc;
        }
#pragma unroll
        for (int i = 0; i < 12; i++) S[i] = ns[i];
    }
    float* T = g_T + ((size_t)sb * NCHAN + ch) * 12;
#pragma unroll
    for (int i = 0; i < 12; i++) T[i] = S[i];
}

__global__ void __launch_bounds__(32, 1) k_scanB() {
    int ch = threadIdx.x;
    float M[144];
#pragma unroll
    for (int e = 0; e < 144; e++) M[e] = g_MS[ch][e];
    float S[12];
#pragma unroll
    for (int i = 0; i < 12; i++) S[i] = 0.f;
    for (int sb = 0; sb < NSB; sb++) {
        float* o = g_sbst + ((size_t)sb * NCHAN + ch) * 12;
#pragma unroll
        for (int i = 0; i < 12; i++) o[i] = S[i];
        const float* T = g_T + ((size_t)sb * NCHAN + ch) * 12;
        float ns[12];
#pragma unroll
        for (int r = 0; r < 12; r++) {
            float acc = T[r];
#pragma unroll
            for (int k2 = 0; k2 < 12; k2++) acc = fmaf(M[r * 12 + k2], S[k2], acc);
            ns[r] = acc;
        }
#pragma unroll
        for (int i = 0; i < 12; i++) S[i] = ns[i];
    }
}

__global__ void __launch_bounds__(256) k_scanC() {
    int idx = blockIdx.x * blockDim.x + threadIdx.x;
    int ch = idx & (NCHAN - 1), sb = idx >> 5;
    float M[144];
#pragma unroll
    for (int e = 0; e < 144; e++) M[e] = g_ML[ch][e];
    float S[12];
    const float* s0 = g_sbst + ((size_t)sb * NCHAN + ch) * 12;
#pragma unroll
    for (int i = 0; i < 12; i++) S[i] = s0[i];
    for (int j = 0; j < SBC; j++) {
        size_t k = (size_t)sb * SBC + j;
        float* o = g_start12 + (k * NCHAN + ch) * 12;
#pragma unroll
        for (int i = 0; i < 12; i++) o[i] = S[i];
        const float* d = g_d12 + (k * NCHAN + ch) * 12;
        float ns[12];
#pragma unroll
        for (int r = 0; r < 12; r++) {
            float acc = d[r];
#pragma unroll
            for (int k2 = 0; k2 < 12; k2++) acc = fmaf(M[r * 12 + k2], S[k2], acc);
            ns[r] = acc;
        }
#pragma unroll
        for (int i = 0; i < 12; i++) S[i] = ns[i];
    }
}

// ---------------- cascade pass 2 + static gain curve ----------------
__global__ void k_pass2(const float* __restrict__ in, float* __restrict__ outy) {
    int c = threadIdx.x;
    int k = blockIdx.x * blockDim.y + threadIdx.y;
    const ChParams& P = g_par[c];
    float b0[6], b1[6], b2[6], a1[6], a2[6];
#pragma unroll
    for (int s = 0; s < 6; s++) { b0[s]=P.b0[s]; b1[s]=P.b1[s]; b2[s]=P.b2[s]; a1[s]=P.a1[s]; a2[s]=P.a2[s]; }
    float thr = P.thr, qr = P.qr, k2c = P.k2, kk = P.kk, inv2k = P.inv2k;
    float s1[6], s2[6];
    const float* st = g_start12 + ((size_t)k * NCHAN + c) * 12;
#pragma unroll
    for (int s = 0; s < 6; s++) { s1[s] = st[2*s]; s2[s] = st[2*s+1]; }
    const float* ip = in   + (size_t)k * CHUNK * NCHAN + c;
    float*       op = outy + (size_t)k * CHUNK * NCHAN + c;
    float*       gp = g_gc + (size_t)k * CHUNK * NCHAN + c;
#pragma unroll 4
    for (int t = 0; t < CHUNK; t++) {
        float v = ip[(size_t)t * NCHAN];
#pragma unroll
        for (int s = 0; s < 6; s++) {
            float y = fmaf(b0[s], v, s1[s]);
            s1[s] = fmaf(-a1[s], y, fmaf(b1[s], v, s2[s]));
            s2[s] = fmaf(-a2[s], y, b2[s] * v);
            v = y;
        }
        op[(size_t)t * NCHAN] = v;
        float av  = fmaxf(fabsf(v), 1e-8f);
        float xdb = 6.0205999132796239f * __log2f(av);
        float d   = xdb - thr;
        float t1  = d + k2c;
        float mid = qr * t1 * t1 * inv2k;
        float hi  = qr * d;
        float gcv = (t1 <= 0.f) ? 0.f : ((t1 >= kk) ? hi : mid);
        gp[(size_t)t * NCHAN] = gcv;
    }
}

// ---------------- envelope stage 1: per-block max-affine intercept DP (EU=32) ----------------
__global__ void __launch_bounds__(256) k_env1() {
    int idx = blockIdx.x * blockDim.x + threadIdx.x;   // ENB*NCHAN threads
    int c = idx & (NCHAN - 1);
    int b = idx >> 5;
    const ChParams& P = g_par[c];
    float aa = P.aa, ar = P.ar, ka = P.ka, kr = P.kr;
    const float* gp = g_gc + (size_t)b * EU * NCHAN + c;
    float I[NLINES];
    {
        float g0 = gp[0];
        I[0] = kr * g0;
        I[1] = ka * g0;
    }
#pragma unroll
    for (int t = 1; t < EU; t++) {
        float g   = gp[(size_t)t * NCHAN];
        float kag = ka * g, krg = kr * g;
        I[t + 1] = fmaf(aa, I[t], kag);
#pragma unroll
        for (int i = NLINES - 2; i >= 1; i--) {
            if (i <= t)
                I[i] = fmaxf(fmaf(aa, I[i - 1], kag), fmaf(ar, I[i], krg));
        }
        I[0] = fmaf(ar, I[0], krg);
    }
    // store shifted intercepts, layout [b][line][chan] (coalesced per line)
    float* gi = g_int + (size_t)b * NLINES * NCHAN + c;
#pragma unroll
    for (int i = 0; i < NLINES; i++)
        gi[i * NCHAN] = I[i] + g_offT[i][c];
}

// ---------------- envelope stage 2: warp-per-channel serial scan ----------------
// state shifted by CSH so all candidates are positive floats -> u32 max valid
__global__ void __launch_bounds__(128, 1) k_env2() {
    int w = threadIdx.x >> 5, l = threadIdx.x & 31;
    int c = blockIdx.x * 4 + w;                  // channel for this warp
    float S  = g_slope[c][l];
    float S2 = g_slope[c][32];
    const float* ip  = g_int + (size_t)l  * NCHAN + c;   // line l of block 0
    const float* ip2 = g_int + (size_t)32 * NCHAN + c;   // line 32 (broadcast)
    const size_t BSTRIDE = (size_t)NLINES * NCHAN;       // floats per block
    float* hb = g_hb + c;

    float cur[EG], cur2[EG], nxt[EG], nxt2[EG];
#pragma unroll
    for (int j = 0; j < EG; j++) {
        cur[j]  = ip [(size_t)j * BSTRIDE];
        cur2[j] = ip2[(size_t)j * BSTRIDE];
    }
    float h = CSH;                                 // h'=h+C, h0=0
    const int NG = ENB / EG;                       // 256 groups
    for (int g = 0; g < NG; g++) {
        if (g + 1 < NG) {
            const float* p  = ip  + (size_t)(g + 1) * EG * BSTRIDE;
            const float* p2 = ip2 + (size_t)(g + 1) * EG * BSTRIDE;
#pragma unroll
            for (int j = 0; j < EG; j++) {
                nxt[j]  = p [(size_t)j * BSTRIDE];
                nxt2[j] = p2[(size_t)j * BSTRIDE];
            }
        }
#pragma unroll
        for (int j = 0; j < EG; j++) {
            if (l == 0) hb[(size_t)(g * EG + j) * NCHAN] = h - CSH;  // boundary BEFORE block
            float v  = fmaf(S,  h, cur[j]);
            float v2 = fmaf(S2, h, cur2[j]);
            v = fmaxf(v, v2);
            unsigned m = __reduce_max_sync(0xffffffffu, __float_as_uint(v));
            h = __uint_as_float(m);
        }
#pragma unroll
        for (int j = 0; j < EG; j++) { cur[j] = nxt[j]; cur2[j] = nxt2[j]; }
    }
}

// ---------------- envelope replay fused with gain/pan/mix ----------------
__global__ void __launch_bounds__(32) k_env3mix(float* __restrict__ out) {
    int c = threadIdx.x;
    int b = blockIdx.x;
    const ChParams& P = g_par[c];
    float aa = P.aa, ar = P.ar, ka = P.ka, kr = P.kr;
    float sigma = P.sigma, mk = P.mk, cth = P.cth, sth = P.sth;
    float h = g_hb[b * NCHAN + c];
    const float* gp = g_gc   + (size_t)b * EU * NCHAN + c;
    const float* yp = g_bufB + (size_t)b * EU * NCHAN + c;
    int batch = c >> 3;
    float* o = out + (size_t)batch * 2 * NS + (size_t)b * EU;
    bool lead = ((c & 7) == 0);
#pragma unroll
    for (int t = 0; t < EU; t++) {
        float gc = gp[(size_t)t * NCHAN];
        float fa = fmaf(aa, h, ka * gc);
        float fr = fmaf(ar, h, kr * gc);
        h = fmaxf(fa, fr);
        float y   = yp[(size_t)t * NCHAN];
        float gdb = fmaf(sigma, h, mk);
        float gl  = exp2f(gdb * 0.16609640474436813f);  // 10^(gdb/20)
        float v   = y * gl;
        float sl = cth * v, sr = sth * v;
        sl += __shfl_xor_sync(0xffffffffu, sl, 1);
        sr += __shfl_xor_sync(0xffffffffu, sr, 1);
        sl += __shfl_xor_sync(0xffffffffu, sl, 2);
        sr += __shfl_xor_sync(0xffffffffu, sr, 2);
        sl += __shfl_xor_sync(0xffffffffu, sl, 4);
        sr += __shfl_xor_sync(0xffffffffu, sr, 4);
        if (lead) {
            o[t]      = sl;
            o[NS + t] = sr;
        }
    }
}

// ---------------- launch ----------------
extern "C" void kernel_launch(void* const* d_in, const int* in_sizes, int n_in,
                              void* d_out, int out_size) {
    const float* tracks = (const float*)d_in[0];
    const float* mparam = (const float*)d_in[1];
    float* out = (float*)d_out;

    float *bufA, *bufB;
    cudaGetSymbolAddress((void**)&bufA, g_bufA);
    cudaGetSymbolAddress((void**)&bufB, g_bufB);

    dim3 pb(32, 8);
    int  pg = NCH / 8;   // 512 blocks

    k_coef<<<1, 32>>>(mparam);
    k_msetup<<<4, 256>>>();
    k_transpose<<<NS / 32, dim3(32, 8)>>>(tracks);
    k_pass1<<<pg, pb>>>(bufA);
    k_scanA<<<(NSB * NCHAN) / 256, 256>>>();
    k_scanB<<<1, 32>>>();
    k_scanC<<<(NSB * NCHAN) / 256, 256>>>();
    k_pass2<<<pg, pb>>>(bufA, bufB);    // y -> bufB, gc -> g_gc

    k_env1<<<(ENB * NCHAN) / 256, 256>>>();
    k_env2<<<8, 128>>>();
    k_env3mix<<<ENB, 32>>>(out);
}

// round 5
// speedup vs baseline: 1.3278x; 1.3278x over previous
#include <cuda_runtime.h>
#include <cstdint>
#include <math.h>

// ---------------- problem constants ----------------
#define FSR    44100.0
#define NS     131072            // samples per channel
#define NCHAN  32                // 4*8 channels
#define CHUNK  32                // samples per chunk (cascade decomposition)
#define NCH    (NS/CHUNK)        // 4096 chunks per channel
#define NSB    64                // superchunks
#define SBC    (NCH/NSB)         // 64 chunks per superchunk
#define EU     32                // envelope block size
#define ENB    (NS/EU)           // 4096 envelope blocks
#define NLINES 33                // EU+1 slope classes
#define LROW   36                // padded line row (floats) -> 144B rows
#define EG     8                 // env2 blocks per load group
#define CSH    512.0f            // positivity shift for u32-max trick

// ---------------- device scratch (static, no allocs) ----------------
__device__ float g_bufA[NCHAN * NS];        // 16 MB : x-gained
__device__ float g_bufB[NCHAN * NS];        // 16 MB : y (post-EQ)
__device__ float g_gc  [NCHAN * NS];        // 16 MB : static gain curve
__device__ float g_int [ENB * NCHAN * LROW];// 18.9 MB : intercepts [b][chan][36]
__device__ float g_hb  [ENB * NCHAN];       // 0.5 MB : block-boundary h
__device__ float g_slope[NCHAN][NLINES];
__device__ float g_offT [NLINES][NCHAN];    // C*(1-S) per line, transposed
__device__ float g_d12   [NCH * NCHAN * 12];
__device__ float g_start12[NCH * NCHAN * 12];
__device__ float g_T     [NSB * NCHAN * 12];
__device__ float g_sbst  [NSB * NCHAN * 12];
__device__ float g_ML[NCHAN][144];             // M^CHUNK
__device__ float g_MS[NCHAN][144];             // M^(CHUNK*SBC)

struct ChParams {
    float b0[6], b1[6], b2[6], a1[6], a2[6];
    float gain;
    float thr, qr, k2, kk, inv2k;      // compressor static curve
    float aa, ar, ka, kr, sigma, mk;   // envelope
    float cth, sth;                    // pan
};
__device__ ChParams g_par[NCHAN];

__device__ const float PLO[26] = {-24.f,-20.f,20.f,0.1f,-20.f,80.f,0.1f,-20.f,200.f,0.1f,-20.f,500.f,0.1f,
                                  -20.f,1000.f,0.1f,-20.f,4000.f,0.1f,-60.f,1.f,1.f,10.f,0.1f,0.f,0.f};
__device__ const float PHI[26] = {24.f,20.f,2000.f,6.f,20.f,2000.f,6.f,20.f,4000.f,6.f,20.f,8000.f,6.f,
                                  20.f,12000.f,6.f,20.f,18000.f,6.f,0.f,10.f,100.f,1000.f,24.f,12.f,1.f};

// ---------------- coefficient setup (32 threads) ----------------
__device__ inline void store_norm(ChParams& P, int s, double b0d, double b1d, double b2d,
                                  double a0d, double a1d, double a2d) {
    P.b0[s] = (float)(b0d / a0d);
    P.b1[s] = (float)(b1d / a0d);
    P.b2[s] = (float)(b2d / a0d);
    P.a1[s] = (float)(a1d / a0d);
    P.a2[s] = (float)(a2d / a0d);
}

__device__ inline void shelf_coeffs(ChParams& P, int s, double g, double f, double q, double sgn) {
    double A  = pow(10.0, g / 40.0);
    double w0 = 2.0 * M_PI * f / FSR;
    double cw = cos(w0), sw = sin(w0);
    double alpha = sw / (2.0 * q);
    double s2 = 2.0 * sqrt(A) * alpha;
    double b0 = A * (A + 1.0 - sgn * (A - 1.0) * cw + s2);
    double b1 = sgn * 2.0 * A * (A - 1.0 - sgn * (A + 1.0) * cw);
    double b2 = A * (A + 1.0 - sgn * (A - 1.0) * cw - s2);
    double a0 = A + 1.0 + sgn * (A - 1.0) * cw + s2;
    double a1 = -sgn * 2.0 * (A - 1.0 + sgn * (A + 1.0) * cw);
    double a2 = A + 1.0 + sgn * (A - 1.0) * cw - s2;
    store_norm(P, s, b0, b1, b2, a0, a1, a2);
}

__device__ inline void peak_coeffs(ChParams& P, int s, double g, double f, double q) {
    double A  = pow(10.0, g / 40.0);
    double w0 = 2.0 * M_PI * f / FSR;
    double cw = cos(w0), sw = sin(w0);
    double alpha = sw / (2.0 * q);
    store_norm(P, s, 1.0 + alpha * A, -2.0 * cw, 1.0 - alpha * A,
                     1.0 + alpha / A, -2.0 * cw, 1.0 - alpha / A);
}

__global__ void k_coef(const float* __restrict__ mp) {
    int c = threadIdx.x;
    if (c >= NCHAN) return;
    double p[26];
#pragma unroll
    for (int i = 0; i < 26; i++) {
        double lo = PLO[i], hi = PHI[i];
        p[i] = (double)mp[c * 26 + i] * (hi - lo) + lo;
    }
    ChParams P;
    P.gain = (float)pow(10.0, p[0] / 20.0);
    shelf_coeffs(P, 0, p[1],  p[2],  p[3],  +1.0);
    peak_coeffs (P, 1, p[4],  p[5],  p[6]);
    peak_coeffs (P, 2, p[7],  p[8],  p[9]);
    peak_coeffs (P, 3, p[10], p[11], p[12]);
    peak_coeffs (P, 4, p[13], p[14], p[15]);
    shelf_coeffs(P, 5, p[16], p[17], p[18], -1.0);

    P.thr  = (float)p[19];
    P.qr   = (float)(1.0 / p[20] - 1.0);
    P.kk   = (float)p[23];
    P.k2   = (float)(p[23] * 0.5);
    P.inv2k= (float)(1.0 / (2.0 * p[23]));
    float aa = (float)exp(-1.0 / (FSR * p[21] * 0.001));
    float ar = (float)exp(-1.0 / (FSR * p[22] * 0.001));
    float omaa = 1.0f - aa;   // replicate reference fp32 rounding
    float omar = 1.0f - ar;
    float sg = (aa >= ar) ? 1.0f : -1.0f;
    P.aa = aa; P.ar = ar;
    P.sigma = sg; P.ka = sg * omaa; P.kr = sg * omar;
    P.mk = (float)p[24];
    double th = p[25] * (M_PI * 0.5);
    P.cth = (float)cos(th);
    P.sth = (float)sin(th);
    g_par[c] = P;
#pragma unroll
    for (int i = 0; i < NLINES; i++) {
        double s = pow((double)aa, (double)i) * pow((double)ar, (double)(EU - i));
        g_slope[c][i] = (float)s;
        g_offT[i][c]  = (float)((double)CSH * (1.0 - s));
    }
}

// ---------------- build M^CHUNK, M^(CHUNK*SBC) per channel (warp/channel) ----------------
__device__ void warp_matmul(double* dst, const double* src, int l) {
    for (int e = l; e < 144; e += 32) {
        int r = e / 12, c2 = e % 12;
        double acc = 0.0;
#pragma unroll
        for (int k = 0; k < 12; k++) acc += src[r * 12 + k] * src[k * 12 + c2];
        dst[e] = acc;
    }
}

__global__ void k_msetup() {          // <<<4, 256>>>
    __shared__ double SA[8][144], SB[8][144];
    int w = threadIdx.x >> 5, l = threadIdx.x & 31;
    int ch = blockIdx.x * 8 + w;
    double* cur = SA[w];
    double* alt = SB[w];
    const ChParams& P = g_par[ch];
    if (l < 12) {
        double s[12], ns[12];
#pragma unroll
        for (int i = 0; i < 12; i++) s[i] = (i == l) ? 1.0 : 0.0;
        double in = 0.0;
#pragma unroll
        for (int st = 0; st < 6; st++) {
            double y = (double)P.b0[st] * in + s[2 * st];
            ns[2 * st]     = (double)P.b1[st] * in - (double)P.a1[st] * y + s[2 * st + 1];
            ns[2 * st + 1] = (double)P.b2[st] * in - (double)P.a2[st] * y;
            in = y;
        }
#pragma unroll
        for (int i = 0; i < 12; i++) cur[i * 12 + l] = ns[i];
    }
    __syncwarp();
    // squarings: M^(2^q); store at q=5 (M^32) and q=11 (M^2048)
    for (int q = 1; q <= 11; q++) {
        warp_matmul(alt, cur, l);
        __syncwarp();
        double* t = cur; cur = alt; alt = t;
        if (q == 5)
            for (int e = l; e < 144; e += 32) g_ML[ch][e] = (float)cur[e];
    }
    for (int e = l; e < 144; e += 32) g_MS[ch][e] = (float)cur[e];
}

// ---------------- transpose [c][t] -> [t][c] with input gain ----------------
__global__ void k_transpose(const float* __restrict__ tracks) {
    __shared__ float tile[32][33];
    int t0 = blockIdx.x * 32;
    int tx = threadIdx.x, ty = threadIdx.y;   // (32, 8)
#pragma unroll
    for (int i = 0; i < 4; i++) {
        int row = ty + i * 8;
        tile[row][tx] = tracks[(size_t)row * NS + t0 + tx];
    }
    __syncthreads();
#pragma unroll
    for (int i = 0; i < 4; i++) {
        int row = ty + i * 8;
        g_bufA[(size_t)(t0 + row) * NCHAN + tx] = tile[tx][row] * g_par[tx].gain;
    }
}

// ---------------- cascade pass 1: zero-init responses ----------------
__global__ void k_pass1(const float* __restrict__ in) {
    int c = threadIdx.x;
    int k = blockIdx.x * blockDim.y + threadIdx.y;
    const ChParams& P = g_par[c];
    float b0[6], b1[6], b2[6], a1[6], a2[6];
#pragma unroll
    for (int s = 0; s < 6; s++) { b0[s]=P.b0[s]; b1[s]=P.b1[s]; b2[s]=P.b2[s]; a1[s]=P.a1[s]; a2[s]=P.a2[s]; }
    float s1[6] = {0,0,0,0,0,0}, s2[6] = {0,0,0,0,0,0};
    const float* ip = in + (size_t)k * CHUNK * NCHAN + c;
#pragma unroll 8
    for (int t = 0; t < CHUNK; t++) {
        float v = ip[(size_t)t * NCHAN];
#pragma unroll
        for (int s = 0; s < 6; s++) {
            float y = fmaf(b0[s], v, s1[s]);
            s1[s] = fmaf(-a1[s], y, fmaf(b1[s], v, s2[s]));
            s2[s] = fmaf(-a2[s], y, b2[s] * v);
            v = y;
        }
    }
    float* d = g_d12 + ((size_t)k * NCHAN + c) * 12;
#pragma unroll
    for (int s = 0; s < 6; s++) { d[2*s] = s1[s]; d[2*s+1] = s2[s]; }
}

// ---------------- hierarchical 12-state scan ----------------
__global__ void __launch_bounds__(256) k_scanA() {
    int idx = blockIdx.x * blockDim.x + threadIdx.x;   // NSB*NCHAN
    int ch = idx & (NCHAN - 1), sb = idx >> 5;
    float M[144];
#pragma unroll
    for (int e = 0; e < 144; e++) M[e] = g_ML[ch][e];
    float S[12];
#pragma unroll
    for (int i = 0; i < 12; i++) S[i] = 0.f;
    for (int j = 0; j < SBC; j++) {
        const float* d = g_d12 + ((size_t)(sb * SBC + j) * NCHAN + ch) * 12;
        float ns[12];
#pragma unroll
        for (int r = 0; r < 12; r++) {
            float acc = d[r];
#pragma unroll
            for (int k2 = 0; k2 < 12; k2++) acc = fmaf(M[r * 12 + k2], S[k2], acc);
            ns[r] = acc;
        }
#pragma unroll
        for (int i = 0; i < 12; i++) S[i] = ns[i];
    }
    float* T = g_T + ((size_t)sb * NCHAN + ch) * 12;
#pragma unroll
    for (int i = 0; i < 12; i++) T[i] = S[i];
}

__global__ void __launch_bounds__(32, 1) k_scanB() {
    int ch = threadIdx.x;
    float M[144];
#pragma unroll
    for (int e = 0; e < 144; e++) M[e] = g_MS[ch][e];
    float S[12];
#pragma unroll
    for (int i = 0; i < 12; i++) S[i] = 0.f;
    for (int sb = 0; sb < NSB; sb++) {
        float* o = g_sbst + ((size_t)sb * NCHAN + ch) * 12;
#pragma unroll
        for (int i = 0; i < 12; i++) o[i] = S[i];
        const float* T = g_T + ((size_t)sb * NCHAN + ch) * 12;
        float ns[12];
#pragma unroll
        for (int r = 0; r < 12; r++) {
            float acc = T[r];
#pragma unroll
            for (int k2 = 0; k2 < 12; k2++) acc = fmaf(M[r * 12 + k2], S[k2], acc);
            ns[r] = acc;
        }
#pragma unroll
        for (int i = 0; i < 12; i++) S[i] = ns[i];
    }
}

__global__ void __launch_bounds__(256) k_scanC() {
    int idx = blockIdx.x * blockDim.x + threadIdx.x;
    int ch = idx & (NCHAN - 1), sb = idx >> 5;
    float M[144];
#pragma unroll
    for (int e = 0; e < 144; e++) M[e] = g_ML[ch][e];
    float S[12];
    const float* s0 = g_sbst + ((size_t)sb * NCHAN + ch) * 12;
#pragma unroll
    for (int i = 0; i < 12; i++) S[i] = s0[i];
    for (int j = 0; j < SBC; j++) {
        size_t k = (size_t)sb * SBC + j;
        float* o = g_start12 + (k * NCHAN + ch) * 12;
#pragma unroll
        for (int i = 0; i < 12; i++) o[i] = S[i];
        const float* d = g_d12 + (k * NCHAN + ch) * 12;
        float ns[12];
#pragma unroll
        for (int r = 0; r < 12; r++) {
            float acc = d[r];
#pragma unroll
            for (int k2 = 0; k2 < 12; k2++) acc = fmaf(M[r * 12 + k2], S[k2], acc);
            ns[r] = acc;
        }
#pragma unroll
        for (int i = 0; i < 12; i++) S[i] = ns[i];
    }
}

// ---------------- cascade pass 2 + static gain curve ----------------
__global__ void k_pass2(const float* __restrict__ in, float* __restrict__ outy) {
    int c = threadIdx.x;
    int k = blockIdx.x * blockDim.y + threadIdx.y;
    const ChParams& P = g_par[c];
    float b0[6], b1[6], b2[6], a1[6], a2[6];
#pragma unroll
    for (int s = 0; s < 6; s++) { b0[s]=P.b0[s]; b1[s]=P.b1[s]; b2[s]=P.b2[s]; a1[s]=P.a1[s]; a2[s]=P.a2[s]; }
    float thr = P.thr, qr = P.qr, k2c = P.k2, kk = P.kk, inv2k = P.inv2k;
    float s1[6], s2[6];
    const float* st = g_start12 + ((size_t)k * NCHAN + c) * 12;
#pragma unroll
    for (int s = 0; s < 6; s++) { s1[s] = st[2*s]; s2[s] = st[2*s+1]; }
    const float* ip = in   + (size_t)k * CHUNK * NCHAN + c;
    float*       op = outy + (size_t)k * CHUNK * NCHAN + c;
    float*       gp = g_gc + (size_t)k * CHUNK * NCHAN + c;
#pragma unroll 4
    for (int t = 0; t < CHUNK; t++) {
        float v = ip[(size_t)t * NCHAN];
#pragma unroll
        for (int s = 0; s < 6; s++) {
            float y = fmaf(b0[s], v, s1[s]);
            s1[s] = fmaf(-a1[s], y, fmaf(b1[s], v, s2[s]));
            s2[s] = fmaf(-a2[s], y, b2[s] * v);
            v = y;
        }
        op[(size_t)t * NCHAN] = v;
        float av  = fmaxf(fabsf(v), 1e-8f);
        float xdb = 6.0205999132796239f * __log2f(av);
        float d   = xdb - thr;
        float t1  = d + k2c;
        float mid = qr * t1 * t1 * inv2k;
        float hi  = qr * d;
        float gcv = (t1 <= 0.f) ? 0.f : ((t1 >= kk) ? hi : mid);
        gp[(size_t)t * NCHAN] = gcv;
    }
}

// ---------------- envelope stage 1: per-block max-affine intercept DP (EU=32) ----------------
// output layout: g_int[b][chan][36] (shifted intercepts, padded rows)
__global__ void __launch_bounds__(256) k_env1() {
    int idx = blockIdx.x * blockDim.x + threadIdx.x;   // ENB*NCHAN threads
    int c = idx & (NCHAN - 1);
    int b = idx >> 5;
    const ChParams& P = g_par[c];
    float aa = P.aa, ar = P.ar, ka = P.ka, kr = P.kr;
    const float* gp = g_gc + (size_t)b * EU * NCHAN + c;
    float I[NLINES];
    {
        float g0 = gp[0];
        I[0] = kr * g0;
        I[1] = ka * g0;
    }
#pragma unroll
    for (int t = 1; t < EU; t++) {
        float g   = gp[(size_t)t * NCHAN];
        float kag = ka * g, krg = kr * g;
        I[t + 1] = fmaf(aa, I[t], kag);
#pragma unroll
        for (int i = NLINES - 2; i >= 1; i--) {
            if (i <= t)
                I[i] = fmaxf(fmaf(aa, I[i - 1], kag), fmaf(ar, I[i], krg));
        }
        I[0] = fmaf(ar, I[0], krg);
    }
    float J[LROW];
#pragma unroll
    for (int i = 0; i < NLINES; i++) J[i] = I[i] + g_offT[i][c];
    J[33] = 0.f; J[34] = 0.f; J[35] = 0.f;
    float4* gi = (float4*)(g_int + ((size_t)b * NCHAN + c) * LROW);
#pragma unroll
    for (int q = 0; q < LROW / 4; q++)
        gi[q] = make_float4(J[4*q], J[4*q+1], J[4*q+2], J[4*q+3]);
}

// ---------------- envelope stage 2: warp-per-channel serial scan ----------------
// lane l evaluates line l (coalesced loads), all lanes also eval broadcast line 32;
// state shifted by CSH so all candidates positive -> u32 redux max valid
__global__ void __launch_bounds__(128, 1) k_env2() {
    int w = threadIdx.x >> 5, l = threadIdx.x & 31;
    int c = blockIdx.x * 4 + w;                  // channel for this warp
    float S  = g_slope[c][l];
    float S2 = g_slope[c][32];
    const float* base = g_int + (size_t)c * LROW;
    const size_t BSTR = (size_t)NCHAN * LROW;    // floats per block
    float* hb = g_hb + c;

    float cur[EG], cur2[EG], nxt[EG], nxt2[EG];
#pragma unroll
    for (int j = 0; j < EG; j++) {
        cur[j]  = base[(size_t)j * BSTR + l];
        cur2[j] = base[(size_t)j * BSTR + 32];
    }
    float h = CSH;                                 // shifted state, h0=0
    const int NG = ENB / EG;                       // 512 groups
    for (int g = 0; g < NG; g++) {
        if (g + 1 < NG) {
            const float* p = base + (size_t)(g + 1) * EG * BSTR;
#pragma unroll
            for (int j = 0; j < EG; j++) {
                nxt[j]  = p[(size_t)j * BSTR + l];
                nxt2[j] = p[(size_t)j * BSTR + 32];
            }
        }
#pragma unroll
        for (int j = 0; j < EG; j++) {
            if (l == 0) hb[(size_t)(g * EG + j) * NCHAN] = h - CSH;  // boundary BEFORE block
            float v  = fmaf(S,  h, cur[j]);
            float v2 = fmaf(S2, h, cur2[j]);
            v = fmaxf(v, v2);
            unsigned m = __reduce_max_sync(0xffffffffu, __float_as_uint(v));
            h = __uint_as_float(m);
        }
#pragma unroll
        for (int j = 0; j < EG; j++) { cur[j] = nxt[j]; cur2[j] = nxt2[j]; }
    }
}

// ---------------- envelope replay fused with gain/pan/mix ----------------
__global__ void __launch_bounds__(32) k_env3mix(float* __restrict__ out) {
    int c = threadIdx.x;
    int b = blockIdx.x;
    const ChParams& P = g_par[c];
    float aa = P.aa, ar = P.ar, ka = P.ka, kr = P.kr;
    float sigma = P.sigma, mk = P.mk, cth = P.cth, sth = P.sth;
    float h = g_hb[b * NCHAN + c];
    const float* gp = g_gc   + (size_t)b * EU * NCHAN + c;
    const float* yp = g_bufB + (size_t)b * EU * NCHAN + c;
    int batch = c >> 3;
    float* o = out + (size_t)batch * 2 * NS + (size_t)b * EU;
    bool lead = ((c & 7) == 0);
#pragma unroll
    for (int t = 0; t < EU; t++) {
        float gc = gp[(size_t)t * NCHAN];
        float fa = fmaf(aa, h, ka * gc);
        float fr = fmaf(ar, h, kr * gc);
        h = fmaxf(fa, fr);
        float y   = yp[(size_t)t * NCHAN];
        float gdb = fmaf(sigma, h, mk);
        float gl  = exp2f(gdb * 0.16609640474436813f);  // 10^(gdb/20)
        float v   = y * gl;
        float sl = cth * v, sr = sth * v;
        sl += __shfl_xor_sync(0xffffffffu, sl, 1);
        sr += __shfl_xor_sync(0xffffffffu, sr, 1);
        sl += __shfl_xor_sync(0xffffffffu, sl, 2);
        sr += __shfl_xor_sync(0xffffffffu, sr, 2);
        sl += __shfl_xor_sync(0xffffffffu, sl, 4);
        sr += __shfl_xor_sync(0xffffffffu, sr, 4);
        if (lead) {
            o[t]      = sl;
            o[NS + t] = sr;
        }
    }
}

// ---------------- launch ----------------
extern "C" void kernel_launch(void* const* d_in, const int* in_sizes, int n_in,
                              void* d_out, int out_size) {
    const float* tracks = (const float*)d_in[0];
    const float* mparam = (const float*)d_in[1];
    float* out = (float*)d_out;

    float *bufA, *bufB;
    cudaGetSymbolAddress((void**)&bufA, g_bufA);
    cudaGetSymbolAddress((void**)&bufB, g_bufB);

    dim3 pb(32, 8);
    int  pg = NCH / 8;   // 512 blocks

    k_coef<<<1, 32>>>(mparam);
    k_msetup<<<4, 256>>>();
    k_transpose<<<NS / 32, dim3(32, 8)>>>(tracks);
    k_pass1<<<pg, pb>>>(bufA);
    k_scanA<<<(NSB * NCHAN) / 256, 256>>>();
    k_scanB<<<1, 32>>>();
    k_scanC<<<(NSB * NCHAN) / 256, 256>>>();
    k_pass2<<<pg, pb>>>(bufA, bufB);    // y -> bufB, gc -> g_gc

    k_env1<<<(ENB * NCHAN) / 256, 256>>>();
    k_env2<<<8, 128>>>();
    k_env3mix<<<ENB, 32>>>(out);
}